// round 8
// baseline (speedup 1.0000x reference)
#include <cuda_runtime.h>

// x: (128, 32, 2, 64, 64) fp32 -> 4096 tiles of (2, 64, 64).
// plaq[i][j] = t0[i][j] + t1[(i+1)%64][j] - t0[i][(j+1)%64] - t1[i][j]
// out[tile] = mean(cos(plaq))
//
// Persistent single-wave (1024 CTAs x 256 thr), 4 tiles per CTA, with ZERO
// barriers in the hot path: the 4 tile rounds are fully unrolled into one
// straight-line body (48 LDG.128 + 64 cos per thread); each round ends in a
// barrier-free warp-shuffle reduction whose partial goes to smem. One single
// __syncthreads at the end, then one 32-lane combine produces all 4 outputs
// (lane = (round<<3)|warp). Warps free-run across tiles, so the DRAM request
// stream has no CTA-wide silence except the ~300-cyc epilogue.

#define THREADS 256
#define GRID_CTAS 1024
#define ROUNDS 4            // 4096 tiles / 1024 CTAs
#define WARPS (THREADS / 32)

__global__ __launch_bounds__(THREADS, 6) void plaq_trace_nobar_kernel(
    const float4* __restrict__ x4, float* __restrict__ out)
{
    const int tid  = threadIdx.x;
    const int lane = tid & 31;
    const int wid  = tid >> 5;
    const int src  = (lane & 16) | ((lane + 1) & 15);   // right-neighbor lane

    __shared__ float wsums[ROUNDS][WARPS];

    #pragma unroll
    for (int r = 0; r < ROUNDS; r++) {
        const float4* __restrict__ t0 =
            x4 + (size_t)(blockIdx.x + r * GRID_CTAS) * 2048;
        const float4* __restrict__ t1 = t0 + 1024;

        float4 A0[4], A1[4], B1[4];
        #pragma unroll
        for (int k = 0; k < 4; k++) {
            const int g  = tid + k * THREADS;      // float4 group 0..1023
            const int i  = g >> 4;                 // row
            const int g1 = (((i + 1) & 63) << 4) | (g & 15);
            A0[k] = t0[g];
            A1[k] = t1[g];
            B1[k] = t1[g1];
        }

        float sum = 0.0f;
        #pragma unroll
        for (int k = 0; k < 4; k++) {
            const float nx = __shfl_sync(0xFFFFFFFFu, A0[k].x, src);
            sum += __cosf(A0[k].x + B1[k].x - A0[k].y - A1[k].x);
            sum += __cosf(A0[k].y + B1[k].y - A0[k].z - A1[k].y);
            sum += __cosf(A0[k].z + B1[k].z - A0[k].w - A1[k].z);
            sum += __cosf(A0[k].w + B1[k].w - nx      - A1[k].w);
        }

        // Barrier-free warp reduction; one smem store per warp per round.
        #pragma unroll
        for (int off = 16; off > 0; off >>= 1)
            sum += __shfl_xor_sync(0xFFFFFFFFu, sum, off);
        if (lane == 0) wsums[r][wid] = sum;
    }

    __syncthreads();        // the only barrier

    // One warp combines all ROUNDS x WARPS partials: lane = (r<<3)|w.
    if (tid < 32) {
        float v = wsums[lane >> 3][lane & 7];
        v += __shfl_xor_sync(0xFFFFFFFFu, v, 4);
        v += __shfl_xor_sync(0xFFFFFFFFu, v, 2);
        v += __shfl_xor_sync(0xFFFFFFFFu, v, 1);
        if ((lane & 7) == 0)
            out[blockIdx.x + (lane >> 3) * GRID_CTAS] = v * (1.0f / 4096.0f);
    }
}

extern "C" void kernel_launch(void* const* d_in, const int* in_sizes, int n_in,
                              void* d_out, int out_size)
{
    const float4* x4 = (const float4*)d_in[0];
    float* out = (float*)d_out;
    plaq_trace_nobar_kernel<<<GRID_CTAS, THREADS>>>(x4, out);
}

// round 9
// speedup vs baseline: 1.8520x; 1.8520x over previous
#include <cuda_runtime.h>

// x: (128, 32, 2, 64, 64) fp32 -> 4096 tiles of (2, 64, 64).
// plaq[i][j] = t0[i][j] + t1[(i+1)%64][j] - t0[i][(j+1)%64] - t1[i][j]
// out[tile] = mean(cos(plaq))
//
// R3 structure (one CTA per tile, 12 independent LDG.128/thread, in-register
// j+1 roll via lane shuffle, i+1 roll = second t1 read) with two deltas:
//  - __launch_bounds__(256, 8): compiler already fits 32 regs, so 8 CTAs/SM
//    = 64 warps/SM (100% occ ceiling) -> more interleaved load batches to
//    fill each warp's cos/reduction tail.
//  - t0 loaded with __ldcs (read-once streaming, evict-first) so t1 (re-read
//    for the row roll) keeps its L1/L2 residency.

#define THREADS 256

__device__ __forceinline__ float4 ldcs4(const float4* p) {
    return __ldcs(p);
}

__global__ __launch_bounds__(THREADS, 8) void plaq_trace_occ8_kernel(
    const float4* __restrict__ x4, float* __restrict__ out)
{
    const int t = blockIdx.x;
    const float4* __restrict__ t0 = x4 + (size_t)t * 2048;  // 1024 float4 each
    const float4* __restrict__ t1 = t0 + 1024;

    const int tid  = threadIdx.x;
    const int lane = tid & 31;
    const int wid  = tid >> 5;
    const int src  = (lane & 16) | ((lane + 1) & 15);  // right-neighbor lane

    float4 A0[4], A1[4], B1[4];

    // 12 independent 16B loads, issued before any consumption.
    #pragma unroll
    for (int k = 0; k < 4; k++) {
        const int g  = tid + k * THREADS;        // float4 group 0..1023
        const int i  = g >> 4;                   // row 0..63
        const int g1 = (((i + 1) & 63) << 4) | (g & 15);
        A0[k] = ldcs4(t0 + g);                   // streaming: read exactly once
        A1[k] = t1[g];                           // re-read via B1 -> keep cached
        B1[k] = t1[g1];
    }

    float sum = 0.0f;
    #pragma unroll
    for (int k = 0; k < 4; k++) {
        const float nx = __shfl_sync(0xFFFFFFFFu, A0[k].x, src);
        sum += __cosf(A0[k].x + B1[k].x - A0[k].y - A1[k].x);
        sum += __cosf(A0[k].y + B1[k].y - A0[k].z - A1[k].y);
        sum += __cosf(A0[k].z + B1[k].z - A0[k].w - A1[k].z);
        sum += __cosf(A0[k].w + B1[k].w - nx      - A1[k].w);
    }

    #pragma unroll
    for (int off = 16; off > 0; off >>= 1)
        sum += __shfl_xor_sync(0xFFFFFFFFu, sum, off);

    __shared__ float warp_sums[THREADS / 32];
    if (lane == 0) warp_sums[wid] = sum;
    __syncthreads();

    if (wid == 0) {
        float s = (lane < (THREADS / 32)) ? warp_sums[lane] : 0.0f;
        #pragma unroll
        for (int off = 4; off > 0; off >>= 1)
            s += __shfl_xor_sync(0xFFFFFFFFu, s, off);
        if (lane == 0) out[t] = s * (1.0f / 4096.0f);
    }
}

extern "C" void kernel_launch(void* const* d_in, const int* in_sizes, int n_in,
                              void* d_out, int out_size)
{
    const float4* x4 = (const float4*)d_in[0];
    float* out = (float*)d_out;
    plaq_trace_occ8_kernel<<<4096, THREADS>>>(x4, out);
}